// round 2
// baseline (speedup 1.0000x reference)
#include <cuda_runtime.h>

#define NB 4
#define NT 1024
#define NC 768
#define NH 12
#define ND 64

// ---------------- scratch (device globals; no allocation allowed) ----------
__device__ float g_q[NB*NH*NT*ND];
__device__ float g_k[NB*NH*NT*ND];
__device__ float g_v[NB*NH*NT*ND];
__device__ float g_yh[NB*NT*NC];   // y pre-proj, [B,T,H*D] layout

// ---------------- QKV GEMM: [4096,768] @ [768,2304], fused bias + scatter --
__global__ __launch_bounds__(256, 1)
void k_qkv(const float* __restrict__ x, const float* __restrict__ W,
           const float* __restrict__ bq)
{
    __shared__ float As[8][128];
    __shared__ float Bs[8][132];
    const int tid = threadIdx.x;
    const int m0 = blockIdx.y * 128;
    const int n0 = blockIdx.x * 128;
    const int ty = tid >> 4, tx = tid & 15;

    float acc[8][8];
#pragma unroll
    for (int i = 0; i < 8; i++)
#pragma unroll
        for (int j = 0; j < 8; j++) acc[i][j] = 0.f;

    const int arow = tid >> 1, ac4 = (tid & 1) * 4;
    const int brow = tid >> 5, bc4 = (tid & 31) * 4;

    for (int k0 = 0; k0 < 768; k0 += 8) {
        float4 a4 = *(const float4*)(x + (size_t)(m0 + arow) * 768 + k0 + ac4);
        float4 b4 = *(const float4*)(W + (size_t)(k0 + brow) * 2304 + n0 + bc4);
        As[ac4 + 0][arow] = a4.x; As[ac4 + 1][arow] = a4.y;
        As[ac4 + 2][arow] = a4.z; As[ac4 + 3][arow] = a4.w;
        *(float4*)&Bs[brow][bc4] = b4;
        __syncthreads();
#pragma unroll
        for (int kk = 0; kk < 8; kk++) {
            float af[8], bf[8];
            *(float4*)&af[0] = *(const float4*)&As[kk][ty * 8];
            *(float4*)&af[4] = *(const float4*)&As[kk][ty * 8 + 4];
            *(float4*)&bf[0] = *(const float4*)&Bs[kk][tx * 8];
            *(float4*)&bf[4] = *(const float4*)&Bs[kk][tx * 8 + 4];
#pragma unroll
            for (int i = 0; i < 8; i++)
#pragma unroll
                for (int j = 0; j < 8; j++)
                    acc[i][j] = fmaf(af[i], bf[j], acc[i][j]);
        }
        __syncthreads();
    }

#pragma unroll
    for (int i = 0; i < 8; i++) {
        const int m = m0 + ty * 8 + i;
        const int b = m >> 10, t = m & 1023;
#pragma unroll
        for (int j = 0; j < 8; j++) {
            const int n = n0 + tx * 8 + j;
            const float v = acc[i][j] + bq[n];
            const int part = n / 768;
            const int rem  = n - part * 768;
            const int h = rem >> 6, d = rem & 63;
            float* dst = (part == 0) ? g_q : (part == 1) ? g_k : g_v;
            dst[(size_t)(((b * NH + h) * NT + t)) * ND + d] = v;
        }
    }
}

// ---------------- proj GEMM: g_yh [4096,768] @ W_proj [768,768] -> y -------
__global__ __launch_bounds__(256, 1)
void k_proj(const float* __restrict__ W, const float* __restrict__ bp,
            float* __restrict__ out)
{
    __shared__ float As[8][128];
    __shared__ float Bs[8][132];
    const int tid = threadIdx.x;
    const int m0 = blockIdx.y * 128;
    const int n0 = blockIdx.x * 128;
    const int ty = tid >> 4, tx = tid & 15;

    float acc[8][8];
#pragma unroll
    for (int i = 0; i < 8; i++)
#pragma unroll
        for (int j = 0; j < 8; j++) acc[i][j] = 0.f;

    const int arow = tid >> 1, ac4 = (tid & 1) * 4;
    const int brow = tid >> 5, bc4 = (tid & 31) * 4;

    for (int k0 = 0; k0 < 768; k0 += 8) {
        float4 a4 = *(const float4*)(g_yh + (size_t)(m0 + arow) * 768 + k0 + ac4);
        float4 b4 = *(const float4*)(W + (size_t)(k0 + brow) * 768 + n0 + bc4);
        As[ac4 + 0][arow] = a4.x; As[ac4 + 1][arow] = a4.y;
        As[ac4 + 2][arow] = a4.z; As[ac4 + 3][arow] = a4.w;
        *(float4*)&Bs[brow][bc4] = b4;
        __syncthreads();
#pragma unroll
        for (int kk = 0; kk < 8; kk++) {
            float af[8], bf[8];
            *(float4*)&af[0] = *(const float4*)&As[kk][ty * 8];
            *(float4*)&af[4] = *(const float4*)&As[kk][ty * 8 + 4];
            *(float4*)&bf[0] = *(const float4*)&Bs[kk][tx * 8];
            *(float4*)&bf[4] = *(const float4*)&Bs[kk][tx * 8 + 4];
#pragma unroll
            for (int i = 0; i < 8; i++)
#pragma unroll
                for (int j = 0; j < 8; j++)
                    acc[i][j] = fmaf(af[i], bf[j], acc[i][j]);
        }
        __syncthreads();
    }

#pragma unroll
    for (int i = 0; i < 8; i++) {
        const int m = m0 + ty * 8 + i;
#pragma unroll
        for (int j = 0; j < 8; j++) {
            const int n = n0 + tx * 8 + j;
            out[(size_t)m * 768 + n] = acc[i][j] + bp[n];
        }
    }
}

// ---------------- fused attention: per (b,h, 64 t-rows) --------------------
#define SPAD 68
#define SMEMB (4 * 64 * SPAD * 4)

__global__ __launch_bounds__(256, 1)
void k_attn(const float* __restrict__ bias, const float* __restrict__ mask,
            float* __restrict__ attn)
{
    extern __shared__ float sm[];
    float* Qs = sm;                  // [d][t]
    float* Ks = sm + 64 * SPAD;      // [d][s]
    float* Vs = sm + 2 * 64 * SPAD;  // [s][d]
    float* Ps = sm + 3 * 64 * SPAD;  // [t][s]

    const int tid = threadIdx.x;
    const int ty = tid >> 4, tx = tid & 15;
    const int b = blockIdx.z, h = blockIdx.y;
    const int t0 = blockIdx.x * 64;
    const int bh = b * NH + h;
    const float scale = 0.125f;

    // load Q tile [64 t][64 d] -> Qs[d][t]
    const float* qg = g_q + (size_t)(bh * NT + t0) * ND;
    for (int e = tid; e < 1024; e += 256) {
        const int t = e >> 4, d4 = (e & 15) * 4;
        float4 v = *(const float4*)(qg + t * 64 + d4);
        Qs[(d4 + 0) * SPAD + t] = v.x;
        Qs[(d4 + 1) * SPAD + t] = v.y;
        Qs[(d4 + 2) * SPAD + t] = v.z;
        Qs[(d4 + 3) * SPAD + t] = v.w;
    }

    float yacc[4][4];
#pragma unroll
    for (int i = 0; i < 4; i++)
#pragma unroll
        for (int j = 0; j < 4; j++) yacc[i][j] = 0.f;
    float rs[4] = {0.f, 0.f, 0.f, 0.f};

    for (int st = 0; st < 16; st++) {
        const int s0 = st * 64;
        const float* kg = g_k + (size_t)(bh * NT + s0) * ND;
        const float* vg = g_v + (size_t)(bh * NT + s0) * ND;
        for (int e = tid; e < 1024; e += 256) {
            const int s = e >> 4, d4 = (e & 15) * 4;
            float4 kv = *(const float4*)(kg + s * 64 + d4);
            Ks[(d4 + 0) * SPAD + s] = kv.x;
            Ks[(d4 + 1) * SPAD + s] = kv.y;
            Ks[(d4 + 2) * SPAD + s] = kv.z;
            Ks[(d4 + 3) * SPAD + s] = kv.w;
            float4 vv = *(const float4*)(vg + s * 64 + d4);
            *(float4*)&Vs[s * SPAD + d4] = vv;
        }
        __syncthreads();

        // S = Q K^T (4x4 microtile)
        float sa[4][4];
#pragma unroll
        for (int i = 0; i < 4; i++)
#pragma unroll
            for (int j = 0; j < 4; j++) sa[i][j] = 0.f;
#pragma unroll 16
        for (int d = 0; d < 64; d++) {
            float4 aq = *(const float4*)&Qs[d * SPAD + ty * 4];
            float4 bk = *(const float4*)&Ks[d * SPAD + tx * 4];
            const float a[4] = {aq.x, aq.y, aq.z, aq.w};
            const float c[4] = {bk.x, bk.y, bk.z, bk.w};
#pragma unroll
            for (int i = 0; i < 4; i++)
#pragma unroll
                for (int j = 0; j < 4; j++)
                    sa[i][j] = fmaf(a[i], c[j], sa[i][j]);
        }

        // p = exp(scale*S + bias + mask); write unnormalized attn; stash in Ps
#pragma unroll
        for (int i = 0; i < 4; i++) {
            const int t = t0 + ty * 4 + i;
            const float4 bb = *(const float4*)(bias + ((size_t)bh * NT + t) * NT + s0 + tx * 4);
            const float4 mm = *(const float4*)(mask + ((size_t)b  * NT + t) * NT + s0 + tx * 4);
            float4 p;
            p.x = expf(fmaf(sa[i][0], scale, bb.x + mm.x));
            p.y = expf(fmaf(sa[i][1], scale, bb.y + mm.y));
            p.z = expf(fmaf(sa[i][2], scale, bb.z + mm.z));
            p.w = expf(fmaf(sa[i][3], scale, bb.w + mm.w));
            rs[i] += (p.x + p.y) + (p.z + p.w);
            *(float4*)(attn + ((size_t)bh * NT + t) * NT + s0 + tx * 4) = p;
            *(float4*)&Ps[(ty * 4 + i) * SPAD + tx * 4] = p;
        }
        __syncthreads();

        // y += P V (thread: rows t=ty*4+i, cols d=tx*4+j)
#pragma unroll 16
        for (int ss = 0; ss < 64; ss++) {
            float4 vv = *(const float4*)&Vs[ss * SPAD + tx * 4];
#pragma unroll
            for (int i = 0; i < 4; i++) {
                const float p = Ps[(ty * 4 + i) * SPAD + ss];
                yacc[i][0] = fmaf(p, vv.x, yacc[i][0]);
                yacc[i][1] = fmaf(p, vv.y, yacc[i][1]);
                yacc[i][2] = fmaf(p, vv.z, yacc[i][2]);
                yacc[i][3] = fmaf(p, vv.w, yacc[i][3]);
            }
        }
        __syncthreads();
    }

    // rowsum reduction across the 16 lanes sharing each t-row
#pragma unroll
    for (int i = 0; i < 4; i++) {
        float v = rs[i];
        v += __shfl_down_sync(0xffffffffu, v, 8, 16);
        v += __shfl_down_sync(0xffffffffu, v, 4, 16);
        v += __shfl_down_sync(0xffffffffu, v, 2, 16);
        v += __shfl_down_sync(0xffffffffu, v, 1, 16);
        v  = __shfl_sync(0xffffffffu, v, 0, 16);
        rs[i] = 1.0f / v;
    }

    // write normalized y head output to g_yh [B,T,H*D]
#pragma unroll
    for (int i = 0; i < 4; i++) {
        const int t = t0 + ty * 4 + i;
        float4 o;
        o.x = yacc[i][0] * rs[i];
        o.y = yacc[i][1] * rs[i];
        o.z = yacc[i][2] * rs[i];
        o.w = yacc[i][3] * rs[i];
        *(float4*)(g_yh + ((size_t)b * NT + t) * NC + h * ND + tx * 4) = o;
    }

    // normalize attn in place (each thread touches only its own prior stores)
    for (int st = 0; st < 16; st++) {
#pragma unroll
        for (int i = 0; i < 4; i++) {
            const int t = t0 + ty * 4 + i;
            float4* p4 = (float4*)(attn + ((size_t)bh * NT + t) * NT + st * 64 + tx * 4);
            float4 v = *p4;
            v.x *= rs[i]; v.y *= rs[i]; v.z *= rs[i]; v.w *= rs[i];
            *p4 = v;
        }
    }
}

// ---------------- launch ---------------------------------------------------
extern "C" void kernel_launch(void* const* d_in, const int* in_sizes, int n_in,
                              void* d_out, int out_size)
{
    const float* x     = (const float*)d_in[0];
    const float* mask  = (const float*)d_in[1];
    const float* bias  = (const float*)d_in[2];
    const float* Wqkv  = (const float*)d_in[3];
    const float* bqkv  = (const float*)d_in[4];
    const float* Wproj = (const float*)d_in[5];
    const float* bproj = (const float*)d_in[6];

    float* y    = (float*)d_out;
    float* attn = y + (size_t)NB * NT * NC;

    cudaFuncSetAttribute(k_attn, cudaFuncAttributeMaxDynamicSharedMemorySize, SMEMB);

    k_qkv <<<dim3(2304 / 128, 4096 / 128), 256>>>(x, Wqkv, bqkv);
    k_attn<<<dim3(NT / 64, NH, NB), 256, SMEMB>>>(bias, mask, attn);
    k_proj<<<dim3(768 / 128, 4096 / 128), 256>>>(Wproj, bproj, y);
}